// round 1
// baseline (speedup 1.0000x reference)
#include <cuda_runtime.h>
#include <math.h>
#include <stdint.h>

// NoisyTopkRouter fused kernel, fp32 SIMT GEMM + epilogue.
//
// C[32768 x 128] = X[32768 x 2048] * W^T, W rows 0..63 = W_route, 64..127 = W_noise.
// Epilogue per token: logits = C[:,0:64]+b_route; noise = C[:,64:128]+b_noise;
// noisy = logits + eps * softplus(noise); top-2; softmax over the two survivors;
// scatter into zeroed 64-wide row; indices appended as floats.

#define MT 128   // tokens per CTA
#define NT 128   // output columns (2*E)
#define KT 32    // K tile
#define THREADS 256

// dynamic smem:
//   phase 1: Xs[KT][MT+1] + Ws[KT][NT+1]  = 2*32*129 floats = 33 KB
//   phase 2: Cs[MT][NT+1]                 = 128*129 floats  = 66 KB  (max)
#define SMEM_BYTES (MT * (NT + 1) * sizeof(float))

__global__ __launch_bounds__(THREADS, 2)
void noisy_topk_router_kernel(const float* __restrict__ x,
                              const float* __restrict__ Wr,
                              const float* __restrict__ br,
                              const float* __restrict__ Wn,
                              const float* __restrict__ bn,
                              const float* __restrict__ eps,
                              float* __restrict__ out,
                              int Ntok, int D, int E, long long out_size)
{
    extern __shared__ float smem[];
    float* Xs = smem;                          // [KT][MT+1]
    float* Ws = smem + KT * (MT + 1);          // [KT][NT+1]
    float* Cs = smem;                          // [MT][NT+1]  (phase 2, reuse)

    const int tid = threadIdx.x;
    const int m0  = blockIdx.x * MT;
    const int tx  = tid & 15;                  // 0..15 -> 8 output cols each
    const int ty  = tid >> 4;                  // 0..15 -> 8 token rows each

    float acc[8][8];
#pragma unroll
    for (int i = 0; i < 8; ++i)
#pragma unroll
        for (int j = 0; j < 8; ++j) acc[i][j] = 0.0f;

    const int lrow = tid >> 3;                 // 0..31 (row within 32-row pass)
    const int lk4  = (tid & 7) * 4;            // k offset 0,4,...,28

    const int nIter = D / KT;
    for (int kt = 0; kt < nIter; ++kt) {
        const int k0 = kt * KT;
        if (kt) __syncthreads();               // previous compute done before overwrite

        // ---- load X tile [MT x KT], store transposed Xs[k][m], pad stride 129 ----
#pragma unroll
        for (int p = 0; p < 4; ++p) {
            const int m = p * 32 + lrow;
            float4 v = *reinterpret_cast<const float4*>(
                &x[(size_t)(m0 + m) * D + k0 + lk4]);
            Xs[(lk4 + 0) * (MT + 1) + m] = v.x;
            Xs[(lk4 + 1) * (MT + 1) + m] = v.y;
            Xs[(lk4 + 2) * (MT + 1) + m] = v.z;
            Xs[(lk4 + 3) * (MT + 1) + m] = v.w;
        }
        // ---- load W tile [NT x KT] (route rows then noise rows), transposed ----
#pragma unroll
        for (int p = 0; p < 4; ++p) {
            const int n = p * 32 + lrow;
            const float* Wp = (n < E) ? &Wr[(size_t)n * D] : &Wn[(size_t)(n - E) * D];
            float4 v = *reinterpret_cast<const float4*>(&Wp[k0 + lk4]);
            Ws[(lk4 + 0) * (NT + 1) + n] = v.x;
            Ws[(lk4 + 1) * (NT + 1) + n] = v.y;
            Ws[(lk4 + 2) * (NT + 1) + n] = v.z;
            Ws[(lk4 + 3) * (NT + 1) + n] = v.w;
        }
        __syncthreads();

        // ---- 128x128x32 compute, 8x8 micro-tile per thread ----
#pragma unroll
        for (int k = 0; k < KT; ++k) {
            float a[8], b[8];
#pragma unroll
            for (int i = 0; i < 8; ++i) a[i] = Xs[k * (MT + 1) + ty * 8 + i];
#pragma unroll
            for (int j = 0; j < 8; ++j) b[j] = Ws[k * (NT + 1) + tx * 8 + j];
#pragma unroll
            for (int i = 0; i < 8; ++i)
#pragma unroll
                for (int j = 0; j < 8; ++j)
                    acc[i][j] = fmaf(a[i], b[j], acc[i][j]);
        }
    }
    __syncthreads();

    // ---- stage accumulators to smem so one thread owns a whole token row ----
#pragma unroll
    for (int i = 0; i < 8; ++i)
#pragma unroll
        for (int j = 0; j < 8; ++j)
            Cs[(ty * 8 + i) * (NT + 1) + tx * 8 + j] = acc[i][j];
    __syncthreads();

    // ---- epilogue: one thread per token ----
    if (tid < MT) {
        const int tok = m0 + tid;
        const float* crow = &Cs[tid * (NT + 1)];

        float v1 = -INFINITY, v2 = -INFINITY;
        int   i1 = -1, i2 = -1;
        for (int e = 0; e < E; ++e) {
            const float lg = crow[e] + br[e];
            const float ns = crow[E + e] + bn[e];
            // jax.nn.softplus(x) = max(x,0) + log1p(exp(-|x|))
            const float sp = fmaxf(ns, 0.0f) + log1pf(expf(-fabsf(ns)));
            const float nv = lg + eps[(size_t)tok * E + e] * sp;
            if (nv > v1) { v2 = v1; i2 = i1; v1 = nv; i1 = e; }
            else if (nv > v2) { v2 = nv; i2 = e; }
        }

        // softmax over {v1, v2} with -inf elsewhere (matches jax softmax numerics)
        const float ed = expf(v2 - v1);
        const float s  = 1.0f + ed;
        const float p1 = 1.0f / s;
        const float p2 = ed / s;

        float* orow = out + (size_t)tok * E;
        for (int e4 = 0; e4 < E; e4 += 4) {
            float vv[4] = {0.0f, 0.0f, 0.0f, 0.0f};
            if (i1 >= e4 && i1 < e4 + 4) vv[i1 - e4] = p1;
            if (i2 >= e4 && i2 < e4 + 4) vv[i2 - e4] = p2;
            *reinterpret_cast<float4*>(orow + e4) =
                make_float4(vv[0], vv[1], vv[2], vv[3]);
        }

        const long long ibase = (long long)Ntok * E;
        if (out_size >= ibase + (long long)Ntok * 2) {
            out[ibase + (long long)tok * 2 + 0] = (float)i1;
            out[ibase + (long long)tok * 2 + 1] = (float)i2;
        }
    }
}

extern "C" void kernel_launch(void* const* d_in, const int* in_sizes, int n_in,
                              void* d_out, int out_size)
{
    const float* x   = (const float*)d_in[0];
    const float* Wr  = (const float*)d_in[1];
    const float* br  = (const float*)d_in[2];
    const float* Wn  = (const float*)d_in[3];
    const float* bn  = (const float*)d_in[4];
    const float* eps = (const float*)d_in[5];
    float* out = (float*)d_out;

    const int E    = in_sizes[2];              // 64
    const int D    = in_sizes[1] / E;          // 2048
    const int Ntok = in_sizes[0] / D;          // 32768

    static int smem_configured = 0;            // idempotent attribute set (not a work guard)
    if (!smem_configured) {
        cudaFuncSetAttribute(noisy_topk_router_kernel,
                             cudaFuncAttributeMaxDynamicSharedMemorySize,
                             (int)SMEM_BYTES);
        smem_configured = 1;
    }

    const int grid = Ntok / MT;                // 256 CTAs
    noisy_topk_router_kernel<<<grid, THREADS, SMEM_BYTES>>>(
        x, Wr, br, Wn, bn, eps, out, Ntok, D, E, (long long)out_size);
}

// round 3
// speedup vs baseline: 1.0500x; 1.0500x over previous
#include <cuda_runtime.h>
#include <math.h>
#include <stdint.h>

// NoisyTopkRouter — TF32x3 split-fp32 GEMM via mma.sync (legacy tensor path,
// baseline PTX: tcgen05 is unavailable because the harness targets compute_103).
//
// C[32768 x 128] = X[32768 x 2048] * W^T  (W rows 0..63 = W_route, 64..127 = W_noise)
// computed as hi*hi + hi*lo + lo*hi TF32 passes (error ~2^-22 per product -> fp32-grade).
// Epilogue: noisy = logits + eps*softplus(noise); top-2; 2-way softmax scatter.

#define MT      128            // tokens per CTA
#define KT      32             // K per smem tile
#define THREADS 256
#define PADC    130            // epilogue Cs row stride (floats)

// smem tile layout: (hi,lo) uint2 pairs, 8B-unit offset(m,k) = (k>>2)*KGS + m*4 + (k&3)
#define KGS    516             // 8B units per k-group block (4*128 + 4 pad)
#define TILE8  (8 * KGS)       // 4128 8B-units per operand tile (KT/4 = 8 groups)
#define TILEB  (TILE8 * 8)     // 33024 bytes
#define BUFB   (2 * TILEB)     // X tile + W tile = 66048 bytes
#define SMEMB  (2 * BUFB)      // double buffered = 132096 bytes

static __device__ __forceinline__ int toff(int m, int k) {
    return ((k >> 2) * KGS) + (m << 2) + (k & 3);
}

static __device__ __forceinline__ uint32_t f2tf32(float x) {
    uint32_t r;
    asm("cvt.rna.tf32.f32 %0, %1;" : "=r"(r) : "f"(x));
    return r;
}

static __device__ __forceinline__ void mma_tf32(float* d,
                                                const uint32_t a0, const uint32_t a1,
                                                const uint32_t a2, const uint32_t a3,
                                                const uint32_t b0, const uint32_t b1) {
    asm volatile(
        "mma.sync.aligned.m16n8k8.row.col.f32.tf32.tf32.f32 "
        "{%0,%1,%2,%3}, {%4,%5,%6,%7}, {%8,%9}, {%0,%1,%2,%3};"
        : "+f"(d[0]), "+f"(d[1]), "+f"(d[2]), "+f"(d[3])
        : "r"(a0), "r"(a1), "r"(a2), "r"(a3), "r"(b0), "r"(b1));
}

// split one float4 into hi/lo tf32 and store as 2 uint4 (4 adjacent (hi,lo) pairs)
static __device__ __forceinline__ void split_store(char* base, int byteoff, float4 v) {
    uint32_t hx = f2tf32(v.x), hy = f2tf32(v.y), hz = f2tf32(v.z), hw = f2tf32(v.w);
    uint32_t lx = f2tf32(v.x - __uint_as_float(hx));
    uint32_t ly = f2tf32(v.y - __uint_as_float(hy));
    uint32_t lz = f2tf32(v.z - __uint_as_float(hz));
    uint32_t lw = f2tf32(v.w - __uint_as_float(hw));
    *reinterpret_cast<uint4*>(base + byteoff)      = make_uint4(hx, lx, hy, ly);
    *reinterpret_cast<uint4*>(base + byteoff + 16) = make_uint4(hz, lz, hw, lw);
}

__global__ __launch_bounds__(THREADS, 1)
void noisy_topk_router_mma(const float* __restrict__ x,
                           const float* __restrict__ Wr,
                           const float* __restrict__ br,
                           const float* __restrict__ Wn,
                           const float* __restrict__ bn,
                           const float* __restrict__ eps,
                           float* __restrict__ out,
                           int Ntok, int D, int E, long long out_size)
{
    extern __shared__ char smem[];

    const int tid  = threadIdx.x;
    const int wid  = tid >> 5;
    const int lane = tid & 31;
    const int gid  = lane >> 2;     // 0..7
    const int tig  = lane & 3;      // 0..3
    const int wm   = wid & 3;       // warp row  (32 tokens)
    const int wn   = wid >> 2;      // warp col  (64 outputs)
    const int m0   = blockIdx.x * MT;

    // producer indexing: 4 float4 rows per operand per tile
    const int c4 = tid & 7;         // float4 column within 32-float k-window
    const int rb = tid >> 3;        // 0..31 base row

    float acc[2][8][4];
#pragma unroll
    for (int f = 0; f < 2; ++f)
#pragma unroll
        for (int g = 0; g < 8; ++g)
#pragma unroll
            for (int i = 0; i < 4; ++i) acc[f][g][i] = 0.0f;

    const int nTiles = D / KT;      // 64

    float4 xv[4], wv[4];

    // ---- prologue: load tile 0, split+store into buf 0 ----
    {
        const int k0 = 0;
#pragma unroll
        for (int p = 0; p < 4; ++p) {
            const int r = rb + 32 * p;
            xv[p] = *reinterpret_cast<const float4*>(&x[(size_t)(m0 + r) * D + k0 + c4 * 4]);
            const float* Wp = (r < 64) ? &Wr[(size_t)r * D] : &Wn[(size_t)(r - 64) * D];
            wv[p] = *reinterpret_cast<const float4*>(&Wp[k0 + c4 * 4]);
        }
        char* Xb = smem;
        char* Wb = smem + TILEB;
#pragma unroll
        for (int p = 0; p < 4; ++p) {
            const int r   = rb + 32 * p;
            const int off = c4 * (KGS * 8) + r * 32;   // bytes
            split_store(Xb, off, xv[p]);
            split_store(Wb, off, wv[p]);
        }
    }
    __syncthreads();

    for (int kt = 0; kt < nTiles; ++kt) {
        const int b = kt & 1;

        // ---- prefetch next tile's globals into registers ----
        if (kt + 1 < nTiles) {
            const int k0 = (kt + 1) * KT;
#pragma unroll
            for (int p = 0; p < 4; ++p) {
                const int r = rb + 32 * p;
                xv[p] = *reinterpret_cast<const float4*>(&x[(size_t)(m0 + r) * D + k0 + c4 * 4]);
                const float* Wp = (r < 64) ? &Wr[(size_t)r * D] : &Wn[(size_t)(r - 64) * D];
                wv[p] = *reinterpret_cast<const float4*>(&Wp[k0 + c4 * 4]);
            }
        }

        // ---- compute on buffer b ----
        const uint2* Xs = reinterpret_cast<const uint2*>(smem + b * BUFB);
        const uint2* Ws = reinterpret_cast<const uint2*>(smem + b * BUFB + TILEB);

#pragma unroll
        for (int kc = 0; kc < KT; kc += 8) {
            uint32_t Ah[2][4], Al[2][4];
#pragma unroll
            for (int f = 0; f < 2; ++f) {
                const int r = wm * 32 + f * 16 + gid;
                const uint2 v0 = Xs[toff(r,     kc + tig)];
                const uint2 v1 = Xs[toff(r + 8, kc + tig)];
                const uint2 v2 = Xs[toff(r,     kc + tig + 4)];
                const uint2 v3 = Xs[toff(r + 8, kc + tig + 4)];
                Ah[f][0] = v0.x; Ah[f][1] = v1.x; Ah[f][2] = v2.x; Ah[f][3] = v3.x;
                Al[f][0] = v0.y; Al[f][1] = v1.y; Al[f][2] = v2.y; Al[f][3] = v3.y;
            }
#pragma unroll
            for (int g = 0; g < 8; ++g) {
                const int n = wn * 64 + g * 8 + gid;
                const uint2 u0 = Ws[toff(n, kc + tig)];
                const uint2 u1 = Ws[toff(n, kc + tig + 4)];
#pragma unroll
                for (int f = 0; f < 2; ++f) {
                    mma_tf32(acc[f][g], Ah[f][0], Ah[f][1], Ah[f][2], Ah[f][3], u0.x, u1.x); // hi*hi
                    mma_tf32(acc[f][g], Ah[f][0], Ah[f][1], Ah[f][2], Ah[f][3], u0.y, u1.y); // hi*lo
                    mma_tf32(acc[f][g], Al[f][0], Al[f][1], Al[f][2], Al[f][3], u0.x, u1.x); // lo*hi
                }
            }
        }

        // ---- store next tile into the other buffer ----
        if (kt + 1 < nTiles) {
            __syncthreads();   // all warps done reading buffer b^1 (last used at kt-1)
            char* Xb = smem + (b ^ 1) * BUFB;
            char* Wb = Xb + TILEB;
#pragma unroll
            for (int p = 0; p < 4; ++p) {
                const int r   = rb + 32 * p;
                const int off = c4 * (KGS * 8) + r * 32;
                split_store(Xb, off, xv[p]);
                split_store(Wb, off, wv[p]);
            }
            __syncthreads();
        }
    }
    __syncthreads();

    // ---- stage accumulators to smem (reuse tile buffers) ----
    float* Cs = reinterpret_cast<float*>(smem);
#pragma unroll
    for (int f = 0; f < 2; ++f)
#pragma unroll
        for (int g = 0; g < 8; ++g) {
            const int row = wm * 32 + f * 16 + gid;
            const int col = wn * 64 + g * 8 + 2 * tig;
            *reinterpret_cast<float2*>(&Cs[row * PADC + col]) =
                make_float2(acc[f][g][0], acc[f][g][1]);
            *reinterpret_cast<float2*>(&Cs[(row + 8) * PADC + col]) =
                make_float2(acc[f][g][2], acc[f][g][3]);
        }
    __syncthreads();

    // ---- epilogue: one thread per token ----
    if (tid < MT) {
        const int tok = m0 + tid;
        const float* crow = &Cs[tid * PADC];

        float v1 = -INFINITY, v2 = -INFINITY;
        int   i1 = -1, i2 = -1;
#pragma unroll 8
        for (int e = 0; e < 64; ++e) {
            const float lg = crow[e]      + __ldg(&br[e]);
            const float ns = crow[64 + e] + __ldg(&bn[e]);
            const float sp = fmaxf(ns, 0.0f) + log1pf(expf(-fabsf(ns)));
            const float nv = lg + __ldg(&eps[(size_t)tok * 64 + e]) * sp;
            if (nv > v1)      { v2 = v1; i2 = i1; v1 = nv; i1 = e; }
            else if (nv > v2) { v2 = nv; i2 = e; }
        }

        const float ed = expf(v2 - v1);
        const float s  = 1.0f + ed;
        const float p1 = 1.0f / s;
        const float p2 = ed / s;

        float* orow = out + (size_t)tok * 64;
#pragma unroll
        for (int e4 = 0; e4 < 64; e4 += 4) {
            float vv[4] = {0.0f, 0.0f, 0.0f, 0.0f};
            if (i1 >= e4 && i1 < e4 + 4) vv[i1 - e4] = p1;
            if (i2 >= e4 && i2 < e4 + 4) vv[i2 - e4] = p2;
            *reinterpret_cast<float4*>(orow + e4) =
                make_float4(vv[0], vv[1], vv[2], vv[3]);
        }

        const long long ibase = (long long)Ntok * 64;
        if (out_size >= ibase + (long long)Ntok * 2) {
            out[ibase + (long long)tok * 2 + 0] = (float)i1;
            out[ibase + (long long)tok * 2 + 1] = (float)i2;
        }
    }
}

extern "C" void kernel_launch(void* const* d_in, const int* in_sizes, int n_in,
                              void* d_out, int out_size)
{
    const float* x   = (const float*)d_in[0];
    const float* Wr  = (const float*)d_in[1];
    const float* br  = (const float*)d_in[2];
    const float* Wn  = (const float*)d_in[3];
    const float* bn  = (const float*)d_in[4];
    const float* eps = (const float*)d_in[5];
    float* out = (float*)d_out;
    (void)n_in;

    const int E    = in_sizes[2];              // 64
    const int D    = in_sizes[1] / E;          // 2048
    const int Ntok = in_sizes[0] / D;          // 32768

    static int configured = 0;                 // idempotent attribute set
    if (!configured) {
        cudaFuncSetAttribute(noisy_topk_router_mma,
                             cudaFuncAttributeMaxDynamicSharedMemorySize, SMEMB);
        configured = 1;
    }

    noisy_topk_router_mma<<<Ntok / MT, THREADS, SMEMB>>>(
        x, Wr, br, Wn, bn, eps, out, Ntok, D, E, (long long)out_size);
}

// round 4
// speedup vs baseline: 1.1445x; 1.0900x over previous
#include <cuda_runtime.h>
#include <math.h>
#include <stdint.h>

// NoisyTopkRouter — TF32x3 split-fp32 GEMM via mma.sync, issue-optimized:
// 16 warps (32x32 warp tiles), pass-major MMA ordering (no acc RAW chains),
// precomputed smem fragment addresses (immediate-offset LDS).
//
// C[32768 x 128] = X[32768 x 2048] * W^T (W rows 0..63 route, 64..127 noise)
// Epilogue: noisy = logits + eps*softplus(noise); top-2; 2-way softmax scatter.

#define MT      128            // tokens per CTA
#define KT      32             // K per smem tile
#define THREADS 512
#define PADC    130            // epilogue Cs row stride (floats)

// smem tile layout: (hi,lo) uint2 pairs, 8B-unit offset(m,k) = (k>>2)*KGS + 4m + (k&3)
#define KGS    516             // 8B units per k-group block (4*128 + 4 pad)
#define TILE8  (8 * KGS)
#define TILEB  (TILE8 * 8)     // 33024 bytes per operand tile
#define BUFB   (2 * TILEB)     // X + W = 66048
#define SMEMB  (2 * BUFB)      // double buffered = 132096

static __device__ __forceinline__ uint32_t f2tf32(float x) {
    uint32_t r;
    asm("cvt.rna.tf32.f32 %0, %1;" : "=r"(r) : "f"(x));
    return r;
}

static __device__ __forceinline__ void mma_tf32(float* d,
                                                const uint32_t a0, const uint32_t a1,
                                                const uint32_t a2, const uint32_t a3,
                                                const uint32_t b0, const uint32_t b1) {
    asm volatile(
        "mma.sync.aligned.m16n8k8.row.col.f32.tf32.tf32.f32 "
        "{%0,%1,%2,%3}, {%4,%5,%6,%7}, {%8,%9}, {%0,%1,%2,%3};"
        : "+f"(d[0]), "+f"(d[1]), "+f"(d[2]), "+f"(d[3])
        : "r"(a0), "r"(a1), "r"(a2), "r"(a3), "r"(b0), "r"(b1));
}

static __device__ __forceinline__ void split_store(char* base, int byteoff, float4 v) {
    uint32_t hx = f2tf32(v.x), hy = f2tf32(v.y), hz = f2tf32(v.z), hw = f2tf32(v.w);
    uint32_t lx = f2tf32(v.x - __uint_as_float(hx));
    uint32_t ly = f2tf32(v.y - __uint_as_float(hy));
    uint32_t lz = f2tf32(v.z - __uint_as_float(hz));
    uint32_t lw = f2tf32(v.w - __uint_as_float(hw));
    *reinterpret_cast<uint4*>(base + byteoff)      = make_uint4(hx, lx, hy, ly);
    *reinterpret_cast<uint4*>(base + byteoff + 16) = make_uint4(hz, lz, hw, lw);
}

__global__ __launch_bounds__(THREADS, 1)
void noisy_topk_router_mma(const float* __restrict__ x,
                           const float* __restrict__ Wr,
                           const float* __restrict__ br,
                           const float* __restrict__ Wn,
                           const float* __restrict__ bn,
                           const float* __restrict__ eps,
                           float* __restrict__ out,
                           int Ntok, int D, int E, long long out_size)
{
    extern __shared__ char smem[];

    const int tid  = threadIdx.x;
    const int wid  = tid >> 5;      // 0..15
    const int lane = tid & 31;
    const int gid  = lane >> 2;     // 0..7
    const int tig  = lane & 3;      // 0..3
    const int wm   = wid & 3;       // warp row  (32 tokens)
    const int wn   = wid >> 2;      // warp col  (32 outputs)
    const int m0   = blockIdx.x * MT;

    // producer indexing: 2 float4 rows per operand per thread per tile
    const int c4 = tid & 7;         // float4 column within 32-float k-window
    const int rb = tid >> 3;        // 0..63 base row

    // fragment base addresses (8B units), loop offsets are immediates
    const int Xb0 = 4 * (wm * 32 + gid) + tig;          // f = 0
    const int Xb1 = Xb0 + 64;                           // f = 1 (+16 rows)
    int Wb[4];
#pragma unroll
    for (int g = 0; g < 4; ++g) Wb[g] = 4 * (wn * 32 + g * 8 + gid) + tig;

    float acc[2][4][4];
#pragma unroll
    for (int f = 0; f < 2; ++f)
#pragma unroll
        for (int g = 0; g < 4; ++g)
#pragma unroll
            for (int i = 0; i < 4; ++i) acc[f][g][i] = 0.0f;

    const int nTiles = D / KT;      // 64
    float4 xv[2], wv[2];

    // ---- prologue: tile 0 -> buffer 0 ----
    {
#pragma unroll
        for (int p = 0; p < 2; ++p) {
            const int r = rb + 64 * p;
            xv[p] = *reinterpret_cast<const float4*>(&x[(size_t)(m0 + r) * D + c4 * 4]);
            const float* Wp = (r < 64) ? &Wr[(size_t)r * D] : &Wn[(size_t)(r - 64) * D];
            wv[p] = *reinterpret_cast<const float4*>(&Wp[c4 * 4]);
        }
#pragma unroll
        for (int p = 0; p < 2; ++p) {
            const int r   = rb + 64 * p;
            const int off = c4 * (KGS * 8) + r * 32;
            split_store(smem, off, xv[p]);
            split_store(smem + TILEB, off, wv[p]);
        }
    }
    __syncthreads();

    for (int kt = 0; kt < nTiles; ++kt) {
        const int b = kt & 1;

        // ---- prefetch next tile's globals into registers ----
        if (kt + 1 < nTiles) {
            const int k0 = (kt + 1) * KT;
#pragma unroll
            for (int p = 0; p < 2; ++p) {
                const int r = rb + 64 * p;
                xv[p] = *reinterpret_cast<const float4*>(&x[(size_t)(m0 + r) * D + k0 + c4 * 4]);
                const float* Wp = (r < 64) ? &Wr[(size_t)r * D] : &Wn[(size_t)(r - 64) * D];
                wv[p] = *reinterpret_cast<const float4*>(&Wp[k0 + c4 * 4]);
            }
        }

        // ---- compute on buffer b ----
        const uint2* Xs = reinterpret_cast<const uint2*>(smem + b * BUFB);
        const uint2* Ws = reinterpret_cast<const uint2*>(smem + b * BUFB + TILEB);

#pragma unroll
        for (int kc = 0; kc < KT; kc += 8) {
            const int o = (kc >> 2) * KGS;

            uint32_t Ah[2][4], Al[2][4];
#pragma unroll
            for (int f = 0; f < 2; ++f) {
                const int base = (f ? Xb1 : Xb0) + o;
                const uint2 v0 = Xs[base];
                const uint2 v1 = Xs[base + 32];
                const uint2 v2 = Xs[base + KGS];
                const uint2 v3 = Xs[base + KGS + 32];
                Ah[f][0] = v0.x; Ah[f][1] = v1.x; Ah[f][2] = v2.x; Ah[f][3] = v3.x;
                Al[f][0] = v0.y; Al[f][1] = v1.y; Al[f][2] = v2.y; Al[f][3] = v3.y;
            }
            uint2 u0[4], u1[4];
#pragma unroll
            for (int g = 0; g < 4; ++g) {
                u0[g] = Ws[Wb[g] + o];
                u1[g] = Ws[Wb[g] + o + KGS];
            }

            // pass-major ordering: 8 independent accumulators between reuses
#pragma unroll
            for (int f = 0; f < 2; ++f)
#pragma unroll
                for (int g = 0; g < 4; ++g)
                    mma_tf32(acc[f][g], Ah[f][0], Ah[f][1], Ah[f][2], Ah[f][3],
                             u0[g].x, u1[g].x);                      // hi*hi
#pragma unroll
            for (int f = 0; f < 2; ++f)
#pragma unroll
                for (int g = 0; g < 4; ++g)
                    mma_tf32(acc[f][g], Ah[f][0], Ah[f][1], Ah[f][2], Ah[f][3],
                             u0[g].y, u1[g].y);                      // hi*lo
#pragma unroll
            for (int f = 0; f < 2; ++f)
#pragma unroll
                for (int g = 0; g < 4; ++g)
                    mma_tf32(acc[f][g], Al[f][0], Al[f][1], Al[f][2], Al[f][3],
                             u0[g].x, u1[g].x);                      // lo*hi
        }

        // ---- store prefetched tile into the other buffer ----
        if (kt + 1 < nTiles) {
            __syncthreads();
            char* Xb = smem + (b ^ 1) * BUFB;
            char* Wbuf = Xb + TILEB;
#pragma unroll
            for (int p = 0; p < 2; ++p) {
                const int r   = rb + 64 * p;
                const int off = c4 * (KGS * 8) + r * 32;
                split_store(Xb, off, xv[p]);
                split_store(Wbuf, off, wv[p]);
            }
            __syncthreads();
        }
    }
    __syncthreads();

    // ---- stage accumulators to smem ----
    float* Cs = reinterpret_cast<float*>(smem);
#pragma unroll
    for (int f = 0; f < 2; ++f)
#pragma unroll
        for (int g = 0; g < 4; ++g) {
            const int row = wm * 32 + f * 16 + gid;
            const int col = wn * 32 + g * 8 + 2 * tig;
            *reinterpret_cast<float2*>(&Cs[row * PADC + col]) =
                make_float2(acc[f][g][0], acc[f][g][1]);
            *reinterpret_cast<float2*>(&Cs[(row + 8) * PADC + col]) =
                make_float2(acc[f][g][2], acc[f][g][3]);
        }
    __syncthreads();

    // ---- epilogue: one thread per token ----
    if (tid < MT) {
        const int tok = m0 + tid;
        const float* crow = &Cs[tid * PADC];

        float v1 = -INFINITY, v2 = -INFINITY;
        int   i1 = -1, i2 = -1;
#pragma unroll 8
        for (int e = 0; e < 64; ++e) {
            const float lg = crow[e]      + __ldg(&br[e]);
            const float ns = crow[64 + e] + __ldg(&bn[e]);
            const float sp = fmaxf(ns, 0.0f) + log1pf(expf(-fabsf(ns)));
            const float nv = lg + __ldg(&eps[(size_t)tok * 64 + e]) * sp;
            if (nv > v1)      { v2 = v1; i2 = i1; v1 = nv; i1 = e; }
            else if (nv > v2) { v2 = nv; i2 = e; }
        }

        const float ed = expf(v2 - v1);
        const float s  = 1.0f + ed;
        const float p1 = 1.0f / s;
        const float p2 = ed / s;

        float* orow = out + (size_t)tok * 64;
#pragma unroll
        for (int e4 = 0; e4 < 64; e4 += 4) {
            float vv[4] = {0.0f, 0.0f, 0.0f, 0.0f};
            if (i1 >= e4 && i1 < e4 + 4) vv[i1 - e4] = p1;
            if (i2 >= e4 && i2 < e4 + 4) vv[i2 - e4] = p2;
            *reinterpret_cast<float4*>(orow + e4) =
                make_float4(vv[0], vv[1], vv[2], vv[3]);
        }

        const long long ibase = (long long)Ntok * 64;
        if (out_size >= ibase + (long long)Ntok * 2) {
            out[ibase + (long long)tok * 2 + 0] = (float)i1;
            out[ibase + (long long)tok * 2 + 1] = (float)i2;
        }
    }
}

extern "C" void kernel_launch(void* const* d_in, const int* in_sizes, int n_in,
                              void* d_out, int out_size)
{
    const float* x   = (const float*)d_in[0];
    const float* Wr  = (const float*)d_in[1];
    const float* br  = (const float*)d_in[2];
    const float* Wn  = (const float*)d_in[3];
    const float* bn  = (const float*)d_in[4];
    const float* eps = (const float*)d_in[5];
    float* out = (float*)d_out;
    (void)n_in;

    const int E    = in_sizes[2];              // 64
    const int D    = in_sizes[1] / E;          // 2048
    const int Ntok = in_sizes[0] / D;          // 32768

    static int configured = 0;                 // idempotent attribute set
    if (!configured) {
        cudaFuncSetAttribute(noisy_topk_router_mma,
                             cudaFuncAttributeMaxDynamicSharedMemorySize, SMEMB);
        configured = 1;
    }

    noisy_topk_router_mma<<<Ntok / MT, THREADS, SMEMB>>>(
        x, Wr, br, Wn, bn, eps, out, Ntok, D, E, (long long)out_size);
}

// round 5
// speedup vs baseline: 1.1560x; 1.0100x over previous
#include <cuda_runtime.h>
#include <math.h>
#include <stdint.h>

// NoisyTopkRouter — TF32x3 split-fp32 via mma.sync.
// R5: raw-fp32 smem tiles (split at fragment load), cp.async 3-stage pipeline,
// 256-thread CTAs with 2 CTAs/SM co-residency, conflict-free LDS.32 frags.
//
// C[32768 x 128] = X[32768 x 2048] * W^T (W rows 0..63 route, 64..127 noise)
// Epilogue: noisy = logits + eps*softplus(noise); top-2; 2-way softmax scatter.

#define MT      128
#define KT      32
#define THREADS 256
#define NSTAGE  3
#define SROW    36                       // floats per smem row (stride), 4 mod 32
#define OPB     (128 * SROW * 4)         // one operand tile = 18432 B
#define STAGEB  (2 * OPB)                // X + W = 36864 B
#define SMEMB   (NSTAGE * STAGEB)        // 110592 B
#define PADC    130

static __device__ __forceinline__ uint32_t f2tf32(float x) {
    uint32_t r;
    asm("cvt.rna.tf32.f32 %0, %1;" : "=r"(r) : "f"(x));
    return r;
}
static __device__ __forceinline__ void split2(float a, uint32_t& hi, uint32_t& lo) {
    hi = f2tf32(a);
    lo = f2tf32(a - __uint_as_float(hi));
}

static __device__ __forceinline__ void mma_tf32(float* d,
                                                uint32_t a0, uint32_t a1,
                                                uint32_t a2, uint32_t a3,
                                                uint32_t b0, uint32_t b1) {
    asm volatile(
        "mma.sync.aligned.m16n8k8.row.col.f32.tf32.tf32.f32 "
        "{%0,%1,%2,%3}, {%4,%5,%6,%7}, {%8,%9}, {%0,%1,%2,%3};"
        : "+f"(d[0]), "+f"(d[1]), "+f"(d[2]), "+f"(d[3])
        : "r"(a0), "r"(a1), "r"(a2), "r"(a3), "r"(b0), "r"(b1));
}

static __device__ __forceinline__ void cp16(uint32_t saddr, const void* gaddr) {
    asm volatile("cp.async.ca.shared.global [%0], [%1], 16;"
                 :: "r"(saddr), "l"(gaddr));
}

__global__ __launch_bounds__(THREADS, 2)
void noisy_topk_router_mma(const float* __restrict__ x,
                           const float* __restrict__ Wr,
                           const float* __restrict__ br,
                           const float* __restrict__ Wn,
                           const float* __restrict__ bn,
                           const float* __restrict__ eps,
                           float* __restrict__ out,
                           int Ntok, int D, int E, long long out_size)
{
    extern __shared__ char smem[];
    uint32_t smem_u;
    asm("{ .reg .u64 t; cvta.to.shared.u64 t, %1; cvt.u32.u64 %0, t; }"
        : "=r"(smem_u) : "l"(smem));

    const int tid  = threadIdx.x;
    const int wid  = tid >> 5;      // 0..7
    const int lane = tid & 31;
    const int gid  = lane >> 2;     // 0..7
    const int tig  = lane & 3;      // 0..3
    const int wm   = wid & 3;       // warp m-row (32 tokens)
    const int wn   = wid >> 2;      // warp n-col (64 outputs)
    const int m0   = blockIdx.x * MT;

    // producer mapping: row = tid>>1 (0..127), 4 quads of 16B each
    const int prow  = tid >> 1;
    const int pquad = (tid & 1) * 4;
    const float* wsrc = (prow < 64) ? &Wr[(size_t)prow * D] : &Wn[(size_t)(prow - 64) * D];
    const float* xsrc = &x[(size_t)(m0 + prow) * D];
    const uint32_t pxd = smem_u + prow * (SROW * 4) + pquad * 16;
    const uint32_t pwd = pxd + OPB;

    float acc[2][8][4];
#pragma unroll
    for (int f = 0; f < 2; ++f)
#pragma unroll
        for (int g = 0; g < 8; ++g)
#pragma unroll
            for (int i = 0; i < 4; ++i) acc[f][g][i] = 0.0f;

    const int nTiles = D / KT;      // 64

    // ---- prologue: stages 0,1 in flight ----
#pragma unroll
    for (int s = 0; s < 2; ++s) {
        const int k0 = s * KT;
        const uint32_t sb = (uint32_t)(s * STAGEB);
#pragma unroll
        for (int q = 0; q < 4; ++q) {
            cp16(pxd + sb + q * 16, xsrc + k0 + (pquad + q) * 4);
            cp16(pwd + sb + q * 16, wsrc + k0 + (pquad + q) * 4);
        }
        asm volatile("cp.async.commit_group;" ::: "memory");
    }

    int stage = 0;
    for (int kt = 0; kt < nTiles; ++kt) {
        // ---- issue stage kt+2 (or empty group for constant wait depth) ----
        if (kt + 2 < nTiles) {
            const int s2 = (kt + 2 == kt + 2) ? ((stage + 2) % NSTAGE) : 0;
            const int k0 = (kt + 2) * KT;
            const uint32_t sb = (uint32_t)(s2 * STAGEB);
#pragma unroll
            for (int q = 0; q < 4; ++q) {
                cp16(pxd + sb + q * 16, xsrc + k0 + (pquad + q) * 4);
                cp16(pwd + sb + q * 16, wsrc + k0 + (pquad + q) * 4);
            }
        }
        asm volatile("cp.async.commit_group;" ::: "memory");
        asm volatile("cp.async.wait_group 2;" ::: "memory");
        __syncthreads();

        // ---- compute on current stage ----
        const float* Xs = reinterpret_cast<const float*>(smem + stage * STAGEB);
        const float* Ws = reinterpret_cast<const float*>(smem + stage * STAGEB + OPB);
        const float* aB = Xs + (wm * 32 + gid) * SROW + tig;
        const float* wB = Ws + (wn * 64 + gid) * SROW + tig;

#pragma unroll
        for (int kc = 0; kc < KT; kc += 8) {
            uint32_t Ah[2][4], Al[2][4];
#pragma unroll
            for (int f = 0; f < 2; ++f) {
                const float* p = aB + f * 16 * SROW + kc;
                split2(p[0],            Ah[f][0], Al[f][0]);
                split2(p[8 * SROW],     Ah[f][1], Al[f][1]);
                split2(p[4],            Ah[f][2], Al[f][2]);
                split2(p[8 * SROW + 4], Ah[f][3], Al[f][3]);
            }
#pragma unroll
            for (int gh = 0; gh < 2; ++gh) {
                uint32_t Bh[4][2], Bl[4][2];
#pragma unroll
                for (int g4 = 0; g4 < 4; ++g4) {
                    const float* p = wB + (gh * 4 + g4) * 8 * SROW + kc;
                    split2(p[0], Bh[g4][0], Bl[g4][0]);
                    split2(p[4], Bh[g4][1], Bl[g4][1]);
                }
                // pass-major: 8 independent accumulators between reuses
#pragma unroll
                for (int f = 0; f < 2; ++f)
#pragma unroll
                    for (int g4 = 0; g4 < 4; ++g4)
                        mma_tf32(acc[f][gh * 4 + g4],
                                 Ah[f][0], Ah[f][1], Ah[f][2], Ah[f][3],
                                 Bh[g4][0], Bh[g4][1]);              // hi*hi
#pragma unroll
                for (int f = 0; f < 2; ++f)
#pragma unroll
                    for (int g4 = 0; g4 < 4; ++g4)
                        mma_tf32(acc[f][gh * 4 + g4],
                                 Ah[f][0], Ah[f][1], Ah[f][2], Ah[f][3],
                                 Bl[g4][0], Bl[g4][1]);              // hi*lo
#pragma unroll
                for (int f = 0; f < 2; ++f)
#pragma unroll
                    for (int g4 = 0; g4 < 4; ++g4)
                        mma_tf32(acc[f][gh * 4 + g4],
                                 Al[f][0], Al[f][1], Al[f][2], Al[f][3],
                                 Bh[g4][0], Bh[g4][1]);              // lo*hi
            }
        }
        __syncthreads();
        stage = (stage + 1 == NSTAGE) ? 0 : stage + 1;
    }

    // ---- stage accumulators to smem ----
    float* Cs = reinterpret_cast<float*>(smem);
#pragma unroll
    for (int f = 0; f < 2; ++f)
#pragma unroll
        for (int g = 0; g < 8; ++g) {
            const int row = wm * 32 + f * 16 + gid;
            const int col = wn * 64 + g * 8 + 2 * tig;
            *reinterpret_cast<float2*>(&Cs[row * PADC + col]) =
                make_float2(acc[f][g][0], acc[f][g][1]);
            *reinterpret_cast<float2*>(&Cs[(row + 8) * PADC + col]) =
                make_float2(acc[f][g][2], acc[f][g][3]);
        }
    __syncthreads();

    // ---- epilogue: one thread per token ----
    if (tid < MT) {
        const int tok = m0 + tid;
        const float* crow = &Cs[tid * PADC];

        float v1 = -INFINITY, v2 = -INFINITY;
        int   i1 = -1, i2 = -1;
#pragma unroll 8
        for (int e = 0; e < 64; ++e) {
            const float lg = crow[e]      + __ldg(&br[e]);
            const float ns = crow[64 + e] + __ldg(&bn[e]);
            const float sp = fmaxf(ns, 0.0f) + log1pf(expf(-fabsf(ns)));
            const float nv = lg + __ldg(&eps[(size_t)tok * 64 + e]) * sp;
            if (nv > v1)      { v2 = v1; i2 = i1; v1 = nv; i1 = e; }
            else if (nv > v2) { v2 = nv; i2 = e; }
        }

        const float ed = expf(v2 - v1);
        const float s  = 1.0f + ed;
        const float p1 = 1.0f / s;
        const float p2 = ed / s;

        float* orow = out + (size_t)tok * 64;
#pragma unroll
        for (int e4 = 0; e4 < 64; e4 += 4) {
            float vv[4] = {0.0f, 0.0f, 0.0f, 0.0f};
            if (i1 >= e4 && i1 < e4 + 4) vv[i1 - e4] = p1;
            if (i2 >= e4 && i2 < e4 + 4) vv[i2 - e4] = p2;
            *reinterpret_cast<float4*>(orow + e4) =
                make_float4(vv[0], vv[1], vv[2], vv[3]);
        }

        const long long ibase = (long long)Ntok * 64;
        if (out_size >= ibase + (long long)Ntok * 2) {
            out[ibase + (long long)tok * 2 + 0] = (float)i1;
            out[ibase + (long long)tok * 2 + 1] = (float)i2;
        }
    }
}

extern "C" void kernel_launch(void* const* d_in, const int* in_sizes, int n_in,
                              void* d_out, int out_size)
{
    const float* x   = (const float*)d_in[0];
    const float* Wr  = (const float*)d_in[1];
    const float* br  = (const float*)d_in[2];
    const float* Wn  = (const float*)d_in[3];
    const float* bn  = (const float*)d_in[4];
    const float* eps = (const float*)d_in[5];
    float* out = (float*)d_out;
    (void)n_in;

    const int E    = in_sizes[2];              // 64
    const int D    = in_sizes[1] / E;          // 2048
    const int Ntok = in_sizes[0] / D;          // 32768

    static int configured = 0;                 // idempotent attribute set
    if (!configured) {
        cudaFuncSetAttribute(noisy_topk_router_mma,
                             cudaFuncAttributeMaxDynamicSharedMemorySize, SMEMB);
        configured = 1;
    }

    noisy_topk_router_mma<<<Ntok / MT, THREADS, SMEMB>>>(
        x, Wr, br, Wn, bn, eps, out, Ntok, D, E, (long long)out_size);
}

// round 7
// speedup vs baseline: 1.2436x; 1.0758x over previous
#include <cuda_runtime.h>
#include <math.h>
#include <stdint.h>

// NoisyTopkRouter — TF32x3 split-fp32 via mma.sync.
// R7 = R6 with the producer coverage bug fixed (4 cp16/thread/stage = full
// 32-float K rows; R6 only loaded half of each tile).
// 16 warps / 32x32 warp tiles (32-reg acc) + double-buffered fragment pipeline,
// raw-fp32 smem, cp.async 3-stage, pass-major MMA ordering.
//
// C[32768 x 128] = X[32768 x 2048] * W^T (W rows 0..63 route, 64..127 noise)
// Epilogue: noisy = logits + eps*softplus(noise); top-2; 2-way softmax scatter.

#define MT      128
#define KT      32
#define THREADS 512
#define NSTAGE  3
#define SROW    36                       // floats per smem row (stride)
#define OPB     (128 * SROW * 4)         // one operand tile = 18432 B
#define STAGEB  (2 * OPB)                // X + W = 36864 B
#define SMEMB   (NSTAGE * STAGEB)        // 110592 B
#define PADC    130

static __device__ __forceinline__ uint32_t f2tf32(float x) {
    uint32_t r;
    asm("cvt.rna.tf32.f32 %0, %1;" : "=r"(r) : "f"(x));
    return r;
}
static __device__ __forceinline__ void split2(float a, uint32_t& hi, uint32_t& lo) {
    hi = f2tf32(a);
    lo = f2tf32(a - __uint_as_float(hi));
}

static __device__ __forceinline__ void mma_tf32(float* d,
                                                uint32_t a0, uint32_t a1,
                                                uint32_t a2, uint32_t a3,
                                                uint32_t b0, uint32_t b1) {
    asm volatile(
        "mma.sync.aligned.m16n8k8.row.col.f32.tf32.tf32.f32 "
        "{%0,%1,%2,%3}, {%4,%5,%6,%7}, {%8,%9}, {%0,%1,%2,%3};"
        : "+f"(d[0]), "+f"(d[1]), "+f"(d[2]), "+f"(d[3])
        : "r"(a0), "r"(a1), "r"(a2), "r"(a3), "r"(b0), "r"(b1));
}

static __device__ __forceinline__ void cp16(uint32_t saddr, const void* gaddr) {
    asm volatile("cp.async.ca.shared.global [%0], [%1], 16;"
                 :: "r"(saddr), "l"(gaddr));
}

struct Frag {
    uint32_t Ah[2][4], Al[2][4];   // f = 0,1 (16-row halves)
    uint32_t Bh[4][2], Bl[4][2];   // g = 0..3 (8-col groups)
};

static __device__ __forceinline__ void load_frags(Frag& F, const float* aB,
                                                  const float* wB, int kc) {
    float ar[8], brr[8];
#pragma unroll
    for (int f = 0; f < 2; ++f) {
        const float* p = aB + f * 16 * SROW + kc;
        ar[f * 4 + 0] = p[0];
        ar[f * 4 + 1] = p[8 * SROW];
        ar[f * 4 + 2] = p[4];
        ar[f * 4 + 3] = p[8 * SROW + 4];
    }
#pragma unroll
    for (int g = 0; g < 4; ++g) {
        const float* p = wB + g * 8 * SROW + kc;
        brr[g * 2 + 0] = p[0];
        brr[g * 2 + 1] = p[4];
    }
#pragma unroll
    for (int f = 0; f < 2; ++f)
#pragma unroll
        for (int i = 0; i < 4; ++i)
            split2(ar[f * 4 + i], F.Ah[f][i], F.Al[f][i]);
#pragma unroll
    for (int g = 0; g < 4; ++g)
#pragma unroll
        for (int i = 0; i < 2; ++i)
            split2(brr[g * 2 + i], F.Bh[g][i], F.Bl[g][i]);
}

static __device__ __forceinline__ void mma_block(float acc[2][4][4], const Frag& F) {
    // pass-major: 8 independent accumulators between reuses
#pragma unroll
    for (int f = 0; f < 2; ++f)
#pragma unroll
        for (int g = 0; g < 4; ++g)
            mma_tf32(acc[f][g], F.Ah[f][0], F.Ah[f][1], F.Ah[f][2], F.Ah[f][3],
                     F.Bh[g][0], F.Bh[g][1]);                    // hi*hi
#pragma unroll
    for (int f = 0; f < 2; ++f)
#pragma unroll
        for (int g = 0; g < 4; ++g)
            mma_tf32(acc[f][g], F.Ah[f][0], F.Ah[f][1], F.Ah[f][2], F.Ah[f][3],
                     F.Bl[g][0], F.Bl[g][1]);                    // hi*lo
#pragma unroll
    for (int f = 0; f < 2; ++f)
#pragma unroll
        for (int g = 0; g < 4; ++g)
            mma_tf32(acc[f][g], F.Al[f][0], F.Al[f][1], F.Al[f][2], F.Al[f][3],
                     F.Bh[g][0], F.Bh[g][1]);                    // lo*hi
}

__global__ __launch_bounds__(THREADS, 1)
void noisy_topk_router_mma(const float* __restrict__ x,
                           const float* __restrict__ Wr,
                           const float* __restrict__ br,
                           const float* __restrict__ Wn,
                           const float* __restrict__ bn,
                           const float* __restrict__ eps,
                           float* __restrict__ out,
                           int Ntok, int D, int E, long long out_size)
{
    extern __shared__ char smem[];
    uint32_t smem_u;
    asm("{ .reg .u64 t; cvta.to.shared.u64 t, %1; cvt.u32.u64 %0, t; }"
        : "=r"(smem_u) : "l"(smem));

    const int tid  = threadIdx.x;
    const int wid  = tid >> 5;      // 0..15
    const int lane = tid & 31;
    const int gid  = lane >> 2;     // 0..7
    const int tig  = lane & 3;      // 0..3
    const int wm   = wid & 3;       // warp m-row (32 tokens)
    const int wn   = wid >> 2;      // warp n-col (32 outputs)
    const int m0   = blockIdx.x * MT;

    // producer mapping: 4 cp16 per thread per stage.
    // threads 0..255 load X, 256..511 load W. Within a group:
    //   prow = pt>>1 (0..127), pqf = (pt&1)*4 -> quads pqf + {0,8,16,24} floats
    // covers all 32 floats of each row exactly once.
    const int pt    = tid & 255;
    const int prow  = pt >> 1;                  // 0..127
    const int pqf   = (pt & 1) * 4;             // float offset 0 or 4
    const bool isW  = tid >= 256;
    const float* gsrc = isW
        ? ((prow < 64) ? &Wr[(size_t)prow * D + pqf] : &Wn[(size_t)(prow - 64) * D + pqf])
        : &x[(size_t)(m0 + prow) * D + pqf];
    const uint32_t pdst = smem_u + (isW ? OPB : 0) + prow * (SROW * 4) + pqf * 4;

    float acc[2][4][4];
#pragma unroll
    for (int f = 0; f < 2; ++f)
#pragma unroll
        for (int g = 0; g < 4; ++g)
#pragma unroll
            for (int i = 0; i < 4; ++i) acc[f][g][i] = 0.0f;

    const int nTiles = D / KT;      // 64

    // ---- prologue: stages 0,1 in flight ----
#pragma unroll
    for (int s = 0; s < 2; ++s) {
#pragma unroll
        for (int q = 0; q < 4; ++q)
            cp16(pdst + s * STAGEB + q * 32, gsrc + s * KT + q * 8);
        asm volatile("cp.async.commit_group;" ::: "memory");
    }

    int stage = 0;
    for (int kt = 0; kt < nTiles; ++kt) {
        // stage+2 was last computed at iter kt-1; WAR protected by the
        // end-of-compute __syncthreads below.
        if (kt + 2 < nTiles) {
            const int s2 = (stage + 2 >= NSTAGE) ? stage + 2 - NSTAGE : stage + 2;
#pragma unroll
            for (int q = 0; q < 4; ++q)
                cp16(pdst + s2 * STAGEB + q * 32, gsrc + (kt + 2) * KT + q * 8);
        }
        asm volatile("cp.async.commit_group;" ::: "memory");
        asm volatile("cp.async.wait_group 2;" ::: "memory");
        __syncthreads();

        const float* Xs = reinterpret_cast<const float*>(smem + stage * STAGEB);
        const float* Ws = reinterpret_cast<const float*>(smem + stage * STAGEB + OPB);
        const float* aB = Xs + (wm * 32 + gid) * SROW + tig;
        const float* wB = Ws + (wn * 32 + gid) * SROW + tig;

        // ---- fragment-pipelined compute: 4 chunks, double-buffered frags ----
        Frag F0, F1;
        load_frags(F0, aB, wB, 0);
        load_frags(F1, aB, wB, 8);
        mma_block(acc, F0);
        load_frags(F0, aB, wB, 16);
        mma_block(acc, F1);
        load_frags(F1, aB, wB, 24);
        mma_block(acc, F0);
        mma_block(acc, F1);

        __syncthreads();               // WAR: stage overwritten in later iters
        stage = (stage + 1 == NSTAGE) ? 0 : stage + 1;
    }

    // ---- stage accumulators to smem ----
    float* Cs = reinterpret_cast<float*>(smem);
#pragma unroll
    for (int f = 0; f < 2; ++f)
#pragma unroll
        for (int g = 0; g < 4; ++g) {
            const int row = wm * 32 + f * 16 + gid;
            const int col = wn * 32 + g * 8 + 2 * tig;
            *reinterpret_cast<float2*>(&Cs[row * PADC + col]) =
                make_float2(acc[f][g][0], acc[f][g][1]);
            *reinterpret_cast<float2*>(&Cs[(row + 8) * PADC + col]) =
                make_float2(acc[f][g][2], acc[f][g][3]);
        }
    __syncthreads();

    // ---- epilogue: one thread per token ----
    if (tid < MT) {
        const int tok = m0 + tid;
        const float* crow = &Cs[tid * PADC];

        float v1 = -INFINITY, v2 = -INFINITY;
        int   i1 = -1, i2 = -1;
#pragma unroll 8
        for (int e = 0; e < 64; ++e) {
            const float lg = crow[e]      + __ldg(&br[e]);
            const float ns = crow[64 + e] + __ldg(&bn[e]);
            const float sp = fmaxf(ns, 0.0f) + log1pf(expf(-fabsf(ns)));
            const float nv = lg + __ldg(&eps[(size_t)tok * 64 + e]) * sp;
            if (nv > v1)      { v2 = v1; i2 = i1; v1 = nv; i1 = e; }
            else if (nv > v2) { v2 = nv; i2 = e; }
        }

        const float ed = expf(v2 - v1);
        const float s  = 1.0f + ed;
        const float p1 = 1.0f / s;
        const float p2 = ed / s;

        float* orow = out + (size_t)tok * 64;
#pragma unroll
        for (int e4 = 0; e4 < 64; e4 += 4) {
            float vv[4] = {0.0f, 0.0f, 0.0f, 0.0f};
            if (i1 >= e4 && i1 < e4 + 4) vv[i1 - e4] = p1;
            if (i2 >= e4 && i2 < e4 + 4) vv[i2 - e4] = p2;
            *reinterpret_cast<float4*>(orow + e4) =
                make_float4(vv[0], vv[1], vv[2], vv[3]);
        }

        const long long ibase = (long long)Ntok * 64;
        if (out_size >= ibase + (long long)Ntok * 2) {
            out[ibase + (long long)tok * 2 + 0] = (float)i1;
            out[ibase + (long long)tok * 2 + 1] = (float)i2;
        }
    }
}

extern "C" void kernel_launch(void* const* d_in, const int* in_sizes, int n_in,
                              void* d_out, int out_size)
{
    const float* x   = (const float*)d_in[0];
    const float* Wr  = (const float*)d_in[1];
    const float* br  = (const float*)d_in[2];
    const float* Wn  = (const float*)d_in[3];
    const float* bn  = (const float*)d_in[4];
    const float* eps = (const float*)d_in[5];
    float* out = (float*)d_out;
    (void)n_in;

    const int E    = in_sizes[2];              // 64
    const int D    = in_sizes[1] / E;          // 2048
    const int Ntok = in_sizes[0] / D;          // 32768

    static int configured = 0;                 // idempotent attribute set
    if (!configured) {
        cudaFuncSetAttribute(noisy_topk_router_mma,
                             cudaFuncAttributeMaxDynamicSharedMemorySize, SMEMB);
        configured = 1;
    }

    noisy_topk_router_mma<<<Ntok / MT, THREADS, SMEMB>>>(
        x, Wr, br, Wn, bn, eps, out, Ntok, D, E, (long long)out_size);
}